// round 10
// baseline (speedup 1.0000x reference)
#include <cuda_runtime.h>
#include <cstdint>

#define N_NODES 100000
#define N_EDGES 1600000
#define NB 98  // ceil(N_NODES / 1024)

typedef unsigned long long u64;

// ---------------- scratch (no allocations allowed) ----------------
__device__ float g_y[(size_t)N_NODES * 128];   // transformed features [yl | yr]
__device__ float g_h[(size_t)N_NODES * 64];    // layer activations
__device__ int   g_deg[N_NODES];
__device__ int   g_rowp[N_NODES];
__device__ int   g_cursor[N_NODES];
__device__ int   g_csr[N_EDGES];               // src ids grouped by dst
__device__ int   g_bsum[128];
__device__ int   g_boff[128];

// packed fp32x2 FMA: d = a*b + d (elementwise on 2 floats in a 64-bit reg)
__device__ __forceinline__ void fma2(u64& d, u64 a, u64 b) {
    asm("fma.rn.f32x2 %0, %1, %2, %3;" : "=l"(d) : "l"(a), "l"(b), "l"(d));
}

// ---------------- CSR build ----------------
__global__ void k_zero_int(int* __restrict__ p, int n) {
    int i = blockIdx.x * blockDim.x + threadIdx.x;
    if (i < n) p[i] = 0;
}

__global__ void k_hist(const int* __restrict__ ei, int* __restrict__ deg) {
    int i = blockIdx.x * blockDim.x + threadIdx.x;
    if (i < N_EDGES) atomicAdd(deg + ei[N_EDGES + i], 1);
}

__global__ __launch_bounds__(1024) void k_scan_local(
    const int* __restrict__ deg, int* __restrict__ rowp, int* __restrict__ bsum) {
    __shared__ int s[1024];
    int t = threadIdx.x;
    int i = blockIdx.x * 1024 + t;
    int v = (i < N_NODES) ? deg[i] : 0;
    s[t] = v;
    __syncthreads();
#pragma unroll
    for (int d = 1; d < 1024; d <<= 1) {
        int x = (t >= d) ? s[t - d] : 0;
        __syncthreads();
        s[t] += x;
        __syncthreads();
    }
    if (i < N_NODES) rowp[i] = s[t] - v;  // exclusive
    if (t == 1023) bsum[blockIdx.x] = s[1023];
}

__global__ __launch_bounds__(128) void k_scan_bsum(const int* __restrict__ bsum,
                                                   int* __restrict__ boff) {
    __shared__ int s[128];
    int t = threadIdx.x;
    int v = (t < NB) ? bsum[t] : 0;
    s[t] = v;
    __syncthreads();
#pragma unroll
    for (int d = 1; d < 128; d <<= 1) {
        int x = (t >= d) ? s[t - d] : 0;
        __syncthreads();
        s[t] += x;
        __syncthreads();
    }
    if (t < NB) boff[t] = s[t] - v;
}

__global__ void k_scan_add(int* __restrict__ rowp, const int* __restrict__ boff,
                           int* __restrict__ cursor) {
    int i = blockIdx.x * blockDim.x + threadIdx.x;
    if (i < N_NODES) {
        int r = rowp[i] + boff[i >> 10];
        rowp[i] = r;
        cursor[i] = r;
    }
}

__global__ void k_fill(const int* __restrict__ ei, int* __restrict__ cursor,
                       int* __restrict__ csr) {
    int i = blockIdx.x * blockDim.x + threadIdx.x;
    if (i < N_EDGES) {
        int src = ei[i];
        int dst = ei[N_EDGES + i];
        int pos = atomicAdd(cursor + dst, 1);
        csr[pos] = src;
    }
}

// ---------------- GEMM: C[N,NOUT] = A[N,64] @ [Wl | Wr] ----------------
// Block tile: 64 rows x NOUT cols, K=64 (full). 256 threads.
// Inner loop uses fma.rn.f32x2 packed along K: each 64-bit accumulator holds
// (sum over even k, sum over odd k); horizontal add at the end. Full fp32
// precision, half the FMA instruction count vs scalar FFMA (rt 2 -> eff 1).
template <int NOUT>
__global__ __launch_bounds__(256, 2) void k_gemm(
    const float* __restrict__ A, const float* __restrict__ Wl,
    const float* __restrict__ Wr, float* __restrict__ C) {
    constexpr int FOUT = NOUT / 2;
    constexpr int NT = NOUT / 32;
    extern __shared__ float sm[];
    float* As = sm;             // [64][68]  (272B rows, 16B-aligned)
    float* Bt = sm + 64 * 68;   // [NOUT][68], Bt[col][k] = B[k][col]

    const int tid = threadIdx.x;
    const int base = blockIdx.x * 64;

    // load A tile (row-major, contiguous -> float4 loads)
#pragma unroll
    for (int i = 0; i < 4; i++) {
        int lin = tid + i * 256;      // float4 id: 0..1023
        int row = lin >> 4;
        int k4 = lin & 15;
        float4 v = make_float4(0.f, 0.f, 0.f, 0.f);
        if (base + row < N_NODES)
            v = *(const float4*)(A + (size_t)(base + row) * 64 + k4 * 4);
        *(float4*)(As + row * 68 + k4 * 4) = v;
    }
    // load B transposed
#pragma unroll
    for (int i = 0; i < (NOUT * 64) / 256; i++) {
        int lin = tid + i * 256;
        int k = lin / NOUT;
        int col = lin % NOUT;
        float v = (col < FOUT) ? Wl[k * FOUT + col] : Wr[k * FOUT + (col - FOUT)];
        Bt[col * 68 + k] = v;
    }
    __syncthreads();

    const int tm = tid >> 5;  // 0..7 (same within a warp -> As broadcasts)
    const int tn = tid & 31;

    u64 acc[8][NT];
#pragma unroll
    for (int m = 0; m < 8; m++)
#pragma unroll
        for (int j = 0; j < NT; j++) acc[m][j] = 0ull;

#pragma unroll
    for (int k0 = 0; k0 < 64; k0 += 4) {
        ulonglong2 b2[NT];
#pragma unroll
        for (int j = 0; j < NT; j++)
            b2[j] = *(const ulonglong2*)(Bt + (tn + 32 * j) * 68 + k0);
#pragma unroll
        for (int m = 0; m < 8; m++) {
            ulonglong2 a2 = *(const ulonglong2*)(As + (tm * 8 + m) * 68 + k0);
#pragma unroll
            for (int j = 0; j < NT; j++) {
                fma2(acc[m][j], a2.x, b2[j].x);
                fma2(acc[m][j], a2.y, b2[j].y);
            }
        }
    }

#pragma unroll
    for (int m = 0; m < 8; m++) {
        int row = base + tm * 8 + m;
        if (row < N_NODES) {
#pragma unroll
            for (int j = 0; j < NT; j++) {
                float2 p = *(float2*)&acc[m][j];
                C[(size_t)row * NOUT + tn + 32 * j] = p.x + p.y;
            }
        }
    }
}

// ---------------- fused aggregate+combine, F=64 (one warp per node) ----------------
// out[n] = elu?( mean_{s in nbr(n)} yl[s] + yr[n] + b )
__global__ __launch_bounds__(256) void k_agg64(
    const int* __restrict__ rowp, const int* __restrict__ deg,
    const int* __restrict__ csr, const float* __restrict__ Y,
    const float* __restrict__ bias, float* __restrict__ out, int doElu) {
    int warp = (blockIdx.x * blockDim.x + threadIdx.x) >> 5;
    int lane = threadIdx.x & 31;
    if (warp >= N_NODES) return;
    int start = rowp[warp];
    int cnt = deg[warp];
    const float* Ycol = Y + lane * 2;

    float ax = 0.f, ay = 0.f;
    int j = 0;
    for (; j + 4 <= cnt; j += 4) {
        int s0 = __ldg(csr + start + j + 0);
        int s1 = __ldg(csr + start + j + 1);
        int s2 = __ldg(csr + start + j + 2);
        int s3 = __ldg(csr + start + j + 3);
        float2 v0 = *(const float2*)(Ycol + (size_t)s0 * 128);
        float2 v1 = *(const float2*)(Ycol + (size_t)s1 * 128);
        float2 v2 = *(const float2*)(Ycol + (size_t)s2 * 128);
        float2 v3 = *(const float2*)(Ycol + (size_t)s3 * 128);
        ax += v0.x; ay += v0.y;
        ax += v1.x; ay += v1.y;
        ax += v2.x; ay += v2.y;
        ax += v3.x; ay += v3.y;
    }
    for (; j < cnt; j++) {
        int s = __ldg(csr + start + j);
        float2 v = *(const float2*)(Ycol + (size_t)s * 128);
        ax += v.x; ay += v.y;
    }

    float dinv = 1.0f / fmaxf((float)cnt, 1.0f);
    float2 r = *(const float2*)(Y + (size_t)warp * 128 + 64 + lane * 2);
    float2 bb = *(const float2*)(bias + lane * 2);
    float ox = ax * dinv + r.x + bb.x;
    float oy = ay * dinv + r.y + bb.y;
    if (doElu) {
        ox = ox > 0.f ? ox : (__expf(ox) - 1.f);
        oy = oy > 0.f ? oy : (__expf(oy) - 1.f);
    }
    *(float2*)(out + (size_t)warp * 64 + lane * 2) = make_float2(ox, oy);
}

// ---------------- fused aggregate+combine, F=32 (final layer, no ELU) --------------
__global__ __launch_bounds__(256) void k_agg32(
    const int* __restrict__ rowp, const int* __restrict__ deg,
    const int* __restrict__ csr, const float* __restrict__ Y,
    const float* __restrict__ bias, float* __restrict__ out) {
    int warp = (blockIdx.x * blockDim.x + threadIdx.x) >> 5;
    int lane = threadIdx.x & 31;
    if (warp >= N_NODES) return;
    int start = rowp[warp];
    int cnt = deg[warp];
    const float* Ycol = Y + lane;

    float ax = 0.f;
    int j = 0;
    for (; j + 4 <= cnt; j += 4) {
        int s0 = __ldg(csr + start + j + 0);
        int s1 = __ldg(csr + start + j + 1);
        int s2 = __ldg(csr + start + j + 2);
        int s3 = __ldg(csr + start + j + 3);
        ax += Ycol[(size_t)s0 * 64];
        ax += Ycol[(size_t)s1 * 64];
        ax += Ycol[(size_t)s2 * 64];
        ax += Ycol[(size_t)s3 * 64];
    }
    for (; j < cnt; j++) {
        int s = __ldg(csr + start + j);
        ax += Ycol[(size_t)s * 64];
    }

    float dinv = 1.0f / fmaxf((float)cnt, 1.0f);
    float r = Y[(size_t)warp * 64 + 32 + lane];
    out[(size_t)warp * 32 + lane] = ax * dinv + r + bias[lane];
}

// ---------------- host ----------------
extern "C" void kernel_launch(void* const* d_in, const int* in_sizes, int n_in,
                              void* d_out, int out_size) {
    const float* x   = (const float*)d_in[0];
    const int*   ei  = (const int*)d_in[1];
    const float* Wl0 = (const float*)d_in[2];
    const float* Wr0 = (const float*)d_in[3];
    const float* b0  = (const float*)d_in[4];
    const float* Wl1 = (const float*)d_in[5];
    const float* Wr1 = (const float*)d_in[6];
    const float* b1  = (const float*)d_in[7];
    const float* Wl2 = (const float*)d_in[8];
    const float* Wr2 = (const float*)d_in[9];
    const float* b2  = (const float*)d_in[10];
    float* out = (float*)d_out;

    float *y, *h;
    int *deg, *rowp, *cursor, *csr, *bsum, *boff;
    cudaGetSymbolAddress((void**)&y, g_y);
    cudaGetSymbolAddress((void**)&h, g_h);
    cudaGetSymbolAddress((void**)&deg, g_deg);
    cudaGetSymbolAddress((void**)&rowp, g_rowp);
    cudaGetSymbolAddress((void**)&cursor, g_cursor);
    cudaGetSymbolAddress((void**)&csr, g_csr);
    cudaGetSymbolAddress((void**)&bsum, g_bsum);
    cudaGetSymbolAddress((void**)&boff, g_boff);

    const int smem128 = (64 * 68 + 128 * 68) * 4;
    const int smem64  = (64 * 68 + 64 * 68) * 4;
    cudaFuncSetAttribute(k_gemm<128>, cudaFuncAttributeMaxDynamicSharedMemorySize, smem128);
    cudaFuncSetAttribute(k_gemm<64>,  cudaFuncAttributeMaxDynamicSharedMemorySize, smem64);

    const int gemmGrid = (N_NODES + 63) / 64;
    const int aggGrid = (N_NODES * 32 + 255) / 256;  // one warp per node

    // ---- CSR build (every call; deterministic work) ----
    k_zero_int<<<(N_NODES + 255) / 256, 256>>>(deg, N_NODES);
    k_hist<<<(N_EDGES + 255) / 256, 256>>>(ei, deg);
    k_scan_local<<<NB, 1024>>>(deg, rowp, bsum);
    k_scan_bsum<<<1, 128>>>(bsum, boff);
    k_scan_add<<<(N_NODES + 255) / 256, 256>>>(rowp, boff, cursor);
    k_fill<<<(N_EDGES + 255) / 256, 256>>>(ei, cursor, csr);

    // ---- layer 0: x -> h (64) ----
    k_gemm<128><<<gemmGrid, 256, smem128>>>(x, Wl0, Wr0, y);
    k_agg64<<<aggGrid, 256>>>(rowp, deg, csr, y, b0, h, 1);

    // ---- layer 1: h -> h (64) ----
    k_gemm<128><<<gemmGrid, 256, smem128>>>(h, Wl1, Wr1, y);
    k_agg64<<<aggGrid, 256>>>(rowp, deg, csr, y, b1, h, 1);

    // ---- layer 2: h -> out (32, no activation) ----
    k_gemm<64><<<gemmGrid, 256, smem64>>>(h, Wl2, Wr2, y);
    k_agg32<<<aggGrid, 256>>>(rowp, deg, csr, y, b2, out);
}

// round 16
// speedup vs baseline: 1.1923x; 1.1923x over previous
#include <cuda_runtime.h>
#include <cuda_bf16.h>
#include <cstdint>

#define N_NODES 100000
#define N_EDGES 1600000
#define NB 98  // ceil(N_NODES / 1024)

// ---------------- scratch (no allocations allowed) ----------------
__device__ float g_y[(size_t)N_NODES * 128];          // GEMM output [yl | yr] fp32
__device__ __nv_bfloat16 g_ahi[(size_t)N_NODES * 64]; // activation hi part
__device__ __nv_bfloat16 g_alo[(size_t)N_NODES * 64]; // activation lo part
__device__ __nv_bfloat16 g_wbhi[20480];               // W [n][k] bf16 hi: L0@0, L1@8192, L2@16384
__device__ __nv_bfloat16 g_wblo[20480];
__device__ int g_deg[N_NODES];
__device__ int g_rowp[N_NODES];
__device__ int g_cursor[N_NODES];
__device__ int g_csr[N_EDGES];
__device__ int g_bsum[128];

// ---------------- CSR build ----------------
__global__ void k_zero_int(int* __restrict__ p, int n) {
    int i = blockIdx.x * blockDim.x + threadIdx.x;
    if (i < n) p[i] = 0;
}

__global__ void k_hist(const int* __restrict__ ei, int* __restrict__ deg) {
    int i = blockIdx.x * blockDim.x + threadIdx.x;
    if (i < N_EDGES) atomicAdd(deg + ei[N_EDGES + i], 1);
}

__global__ __launch_bounds__(1024) void k_scan_local(
    const int* __restrict__ deg, int* __restrict__ rowp, int* __restrict__ bsum) {
    __shared__ int s[1024];
    int t = threadIdx.x;
    int i = blockIdx.x * 1024 + t;
    int v = (i < N_NODES) ? deg[i] : 0;
    s[t] = v;
    __syncthreads();
#pragma unroll
    for (int d = 1; d < 1024; d <<= 1) {
        int x = (t >= d) ? s[t - d] : 0;
        __syncthreads();
        s[t] += x;
        __syncthreads();
    }
    if (i < N_NODES) rowp[i] = s[t] - v;  // exclusive (block-local)
    if (t == 1023) bsum[blockIdx.x] = s[1023];
}

// add cross-block offsets (computed in-kernel from bsum) and init cursor
__global__ __launch_bounds__(1024) void k_scan_add(
    int* __restrict__ rowp, const int* __restrict__ bsum, int* __restrict__ cursor) {
    __shared__ int boff;
    int b = blockIdx.x;
    int t = threadIdx.x;
    if (t < 32) {
        int part = 0;
        for (int j = t; j < b; j += 32) part += bsum[j];
#pragma unroll
        for (int d = 16; d > 0; d >>= 1)
            part += __shfl_down_sync(0xFFFFFFFF, part, d);
        if (t == 0) boff = part;
    }
    __syncthreads();
    int i = b * 1024 + t;
    if (i < N_NODES) {
        int r = rowp[i] + boff;
        rowp[i] = r;
        cursor[i] = r;
    }
}

__global__ void k_fill(const int* __restrict__ ei, int* __restrict__ cursor,
                       int* __restrict__ csr) {
    int i = blockIdx.x * blockDim.x + threadIdx.x;
    if (i < N_EDGES) {
        int src = ei[i];
        int dst = ei[N_EDGES + i];
        int pos = atomicAdd(cursor + dst, 1);
        csr[pos] = src;
    }
}

// ---------------- bf16 splits ----------------
__global__ void k_split_x(const float* __restrict__ x, __nv_bfloat16* __restrict__ hi,
                          __nv_bfloat16* __restrict__ lo) {
    int i = blockIdx.x * blockDim.x + threadIdx.x;  // over N*32 float2
    if (i >= N_NODES * 32) return;
    float2 v = ((const float2*)x)[i];
    __nv_bfloat16 hx = __float2bfloat16(v.x);
    __nv_bfloat16 hy = __float2bfloat16(v.y);
    __nv_bfloat162 hv; hv.x = hx; hv.y = hy;
    __nv_bfloat162 lv;
    lv.x = __float2bfloat16(v.x - __bfloat162float(hx));
    lv.y = __float2bfloat16(v.y - __bfloat162float(hy));
    ((__nv_bfloat162*)hi)[i] = hv;
    ((__nv_bfloat162*)lo)[i] = lv;
}

// W combined as B[n][k] = (n<f ? Wl[k][n] : Wr[k][n-f]), [N=2f, K=64] bf16 row-major
__global__ void k_split_w(const float* __restrict__ Wl0, const float* __restrict__ Wr0,
                          const float* __restrict__ Wl1, const float* __restrict__ Wr1,
                          const float* __restrict__ Wl2, const float* __restrict__ Wr2,
                          __nv_bfloat16* __restrict__ bh, __nv_bfloat16* __restrict__ bl) {
    int i = blockIdx.x * blockDim.x + threadIdx.x;
    if (i >= 20480) return;
    const float *Wl, *Wr;
    int f, base, li;
    if (i < 8192)       { Wl = Wl0; Wr = Wr0; f = 64; base = 0;     li = i; }
    else if (i < 16384) { Wl = Wl1; Wr = Wr1; f = 64; base = 8192;  li = i - 8192; }
    else                { Wl = Wl2; Wr = Wr2; f = 32; base = 16384; li = i - 16384; }
    int n = li >> 6, k = li & 63;
    float v = (n < f) ? Wl[k * f + n] : Wr[k * f + (n - f)];
    __nv_bfloat16 h = __float2bfloat16(v);
    bh[base + li] = h;
    bl[base + li] = __float2bfloat16(v - __bfloat162float(h));
}

// ---------------- tensor GEMM via mma.sync m16n8k16 bf16, 3-term split --------------
// C[128-tile, NOUT] = A[*,64] @ B^T, B stored [NOUT][64].
// acc += Ahi*Bhi + Alo*Bhi + Ahi*Blo  (fp32 accumulators)
__device__ __forceinline__ void mma16816(float* c, const uint32_t* a, const uint32_t* b) {
    asm volatile(
        "mma.sync.aligned.m16n8k16.row.col.f32.bf16.bf16.f32 "
        "{%0,%1,%2,%3}, {%4,%5,%6,%7}, {%8,%9}, {%0,%1,%2,%3};"
        : "+f"(c[0]), "+f"(c[1]), "+f"(c[2]), "+f"(c[3])
        : "r"(a[0]), "r"(a[1]), "r"(a[2]), "r"(a[3]), "r"(b[0]), "r"(b[1]));
}

template <int NOUT>
__global__ __launch_bounds__(256) void k_mma(
    const __nv_bfloat16* __restrict__ Ahi, const __nv_bfloat16* __restrict__ Alo,
    const __nv_bfloat16* __restrict__ Bhi, const __nv_bfloat16* __restrict__ Blo,
    float* __restrict__ C) {
    constexpr int NT = NOUT / 8;  // n-tiles per warp
    // smem rows padded to 72 bf16 (36 b32 words) -> frag LDS banks (4g+t)%32: conflict-free
    extern __shared__ __align__(16) __nv_bfloat16 sm[];
    __nv_bfloat16* sAh = sm;                 // 128 x 72
    __nv_bfloat16* sAl = sAh + 128 * 72;
    __nv_bfloat16* sBh = sAl + 128 * 72;     // NOUT x 72
    __nv_bfloat16* sBl = sBh + NOUT * 72;

    const int tid = threadIdx.x;
    const int base = blockIdx.x * 128;

    // stage A (hi+lo): 128 rows x 64 bf16 = 8 int4 per row (128 B/row)
    for (int i = tid; i < 1024; i += 256) {
        int row = i >> 3, c = i & 7;
        int node = base + row;
        if (node >= N_NODES) node = N_NODES - 1;
        *(int4*)(sAh + row * 72 + c * 8) = *((const int4*)(Ahi + (size_t)node * 64) + c);
        *(int4*)(sAl + row * 72 + c * 8) = *((const int4*)(Alo + (size_t)node * 64) + c);
    }
    // stage B (hi+lo): NOUT rows x 64 bf16 = 8 int4 per row
    for (int i = tid; i < NOUT * 8; i += 256) {
        int row = i >> 3, c = i & 7;
        *(int4*)(sBh + row * 72 + c * 8) = *((const int4*)(Bhi + row * 64) + c);
        *(int4*)(sBl + row * 72 + c * 8) = *((const int4*)(Blo + row * 64) + c);
    }
    __syncthreads();

    const int wid = tid >> 5, lane = tid & 31;
    const int g = lane >> 2, t = lane & 3;

    const uint32_t* wAh = (const uint32_t*)sAh;
    const uint32_t* wAl = (const uint32_t*)sAl;
    const uint32_t* wBh = (const uint32_t*)sBh;
    const uint32_t* wBl = (const uint32_t*)sBl;

    // preload A fragments for all 4 k-tiles (hi and lo), register-resident
    uint32_t ah[4][4], al[4][4];
    const int arow = (wid * 16 + g) * 36;
#pragma unroll
    for (int kt = 0; kt < 4; kt++) {
        int w0 = arow + kt * 8 + t;
        ah[kt][0] = wAh[w0];
        ah[kt][1] = wAh[w0 + 8 * 36];
        ah[kt][2] = wAh[w0 + 4];
        ah[kt][3] = wAh[w0 + 8 * 36 + 4];
        al[kt][0] = wAl[w0];
        al[kt][1] = wAl[w0 + 8 * 36];
        al[kt][2] = wAl[w0 + 4];
        al[kt][3] = wAl[w0 + 8 * 36 + 4];
    }

    float acc[NT][4];
#pragma unroll
    for (int nt = 0; nt < NT; nt++)
#pragma unroll
        for (int q = 0; q < 4; q++) acc[nt][q] = 0.f;

#pragma unroll
    for (int nt = 0; nt < NT; nt++) {
#pragma unroll
        for (int kt = 0; kt < 4; kt++) {
            int wb = (nt * 8 + g) * 36 + kt * 8 + t;
            uint32_t bh[2] = {wBh[wb], wBh[wb + 4]};
            mma16816(acc[nt], ah[kt], bh);
            mma16816(acc[nt], al[kt], bh);
            uint32_t bl[2] = {wBl[wb], wBl[wb + 4]};
            mma16816(acc[nt], ah[kt], bl);
        }
    }

    // epilogue: c0,c1 -> row (g), cols 2t,2t+1 of n-tile; c2,c3 -> row g+8
    const int r0 = base + wid * 16 + g;
#pragma unroll
    for (int nt = 0; nt < NT; nt++) {
        int col = nt * 8 + 2 * t;
        if (r0 < N_NODES)
            *(float2*)(C + (size_t)r0 * NOUT + col) = make_float2(acc[nt][0], acc[nt][1]);
        if (r0 + 8 < N_NODES)
            *(float2*)(C + (size_t)(r0 + 8) * NOUT + col) = make_float2(acc[nt][2], acc[nt][3]);
    }
}

// ---------------- fused aggregate+combine, F=64, bf16-split output ----------------
__global__ __launch_bounds__(256) void k_agg64(
    const int* __restrict__ rowp, const int* __restrict__ deg,
    const int* __restrict__ csr, const float* __restrict__ Y,
    const float* __restrict__ bias, __nv_bfloat16* __restrict__ ohi,
    __nv_bfloat16* __restrict__ olo) {
    int warp = (blockIdx.x * blockDim.x + threadIdx.x) >> 5;
    int lane = threadIdx.x & 31;
    if (warp >= N_NODES) return;
    int start = rowp[warp];
    int cnt = deg[warp];
    const float* Ycol = Y + lane * 2;

    float ax = 0.f, ay = 0.f;
    int j = 0;
    for (; j + 4 <= cnt; j += 4) {
        int s0 = __ldg(csr + start + j + 0);
        int s1 = __ldg(csr + start + j + 1);
        int s2 = __ldg(csr + start + j + 2);
        int s3 = __ldg(csr + start + j + 3);
        float2 v0 = *(const float2*)(Ycol + (size_t)s0 * 128);
        float2 v1 = *(const float2*)(Ycol + (size_t)s1 * 128);
        float2 v2 = *(const float2*)(Ycol + (size_t)s2 * 128);
        float2 v3 = *(const float2*)(Ycol + (size_t)s3 * 128);
        ax += v0.x; ay += v0.y;
        ax += v1.x; ay += v1.y;
        ax += v2.x; ay += v2.y;
        ax += v3.x; ay += v3.y;
    }
    for (; j < cnt; j++) {
        int s = __ldg(csr + start + j);
        float2 v = *(const float2*)(Ycol + (size_t)s * 128);
        ax += v.x; ay += v.y;
    }

    float dinv = 1.0f / fmaxf((float)cnt, 1.0f);
    float2 r = *(const float2*)(Y + (size_t)warp * 128 + 64 + lane * 2);
    float2 bb = *(const float2*)(bias + lane * 2);
    float ox = ax * dinv + r.x + bb.x;
    float oy = ay * dinv + r.y + bb.y;
    ox = ox > 0.f ? ox : (__expf(ox) - 1.f);
    oy = oy > 0.f ? oy : (__expf(oy) - 1.f);

    __nv_bfloat16 hx = __float2bfloat16(ox);
    __nv_bfloat16 hy = __float2bfloat16(oy);
    __nv_bfloat162 hv; hv.x = hx; hv.y = hy;
    __nv_bfloat162 lv;
    lv.x = __float2bfloat16(ox - __bfloat162float(hx));
    lv.y = __float2bfloat16(oy - __bfloat162float(hy));
    *(__nv_bfloat162*)(ohi + (size_t)warp * 64 + lane * 2) = hv;
    *(__nv_bfloat162*)(olo + (size_t)warp * 64 + lane * 2) = lv;
}

// ---------------- fused aggregate+combine, F=32 (final layer, fp32 out) -----------
__global__ __launch_bounds__(256) void k_agg32(
    const int* __restrict__ rowp, const int* __restrict__ deg,
    const int* __restrict__ csr, const float* __restrict__ Y,
    const float* __restrict__ bias, float* __restrict__ out) {
    int warp = (blockIdx.x * blockDim.x + threadIdx.x) >> 5;
    int lane = threadIdx.x & 31;
    if (warp >= N_NODES) return;
    int start = rowp[warp];
    int cnt = deg[warp];
    const float* Ycol = Y + lane;

    float ax = 0.f;
    int j = 0;
    for (; j + 4 <= cnt; j += 4) {
        int s0 = __ldg(csr + start + j + 0);
        int s1 = __ldg(csr + start + j + 1);
        int s2 = __ldg(csr + start + j + 2);
        int s3 = __ldg(csr + start + j + 3);
        ax += Ycol[(size_t)s0 * 64];
        ax += Ycol[(size_t)s1 * 64];
        ax += Ycol[(size_t)s2 * 64];
        ax += Ycol[(size_t)s3 * 64];
    }
    for (; j < cnt; j++) {
        int s = __ldg(csr + start + j);
        ax += Ycol[(size_t)s * 64];
    }

    float dinv = 1.0f / fmaxf((float)cnt, 1.0f);
    float r = Y[(size_t)warp * 64 + 32 + lane];
    out[(size_t)warp * 32 + lane] = ax * dinv + r + bias[lane];
}

// ---------------- host ----------------
extern "C" void kernel_launch(void* const* d_in, const int* in_sizes, int n_in,
                              void* d_out, int out_size) {
    const float* x   = (const float*)d_in[0];
    const int*   ei  = (const int*)d_in[1];
    const float* Wl0 = (const float*)d_in[2];
    const float* Wr0 = (const float*)d_in[3];
    const float* b0  = (const float*)d_in[4];
    const float* Wl1 = (const float*)d_in[5];
    const float* Wr1 = (const float*)d_in[6];
    const float* b1  = (const float*)d_in[7];
    const float* Wl2 = (const float*)d_in[8];
    const float* Wr2 = (const float*)d_in[9];
    const float* b2  = (const float*)d_in[10];
    float* out = (float*)d_out;

    float* y;
    __nv_bfloat16 *ahi, *alo, *wbhi, *wblo;
    int *deg, *rowp, *cursor, *csr, *bsum;
    cudaGetSymbolAddress((void**)&y, g_y);
    cudaGetSymbolAddress((void**)&ahi, g_ahi);
    cudaGetSymbolAddress((void**)&alo, g_alo);
    cudaGetSymbolAddress((void**)&wbhi, g_wbhi);
    cudaGetSymbolAddress((void**)&wblo, g_wblo);
    cudaGetSymbolAddress((void**)&deg, g_deg);
    cudaGetSymbolAddress((void**)&rowp, g_rowp);
    cudaGetSymbolAddress((void**)&cursor, g_cursor);
    cudaGetSymbolAddress((void**)&csr, g_csr);
    cudaGetSymbolAddress((void**)&bsum, g_bsum);

    const int smem128 = (128 * 72 * 2 + 128 * 72 * 2) * 2;  // 73728
    const int smem64  = (128 * 72 * 2 + 64 * 72 * 2) * 2;   // 55296
    cudaFuncSetAttribute(k_mma<128>, cudaFuncAttributeMaxDynamicSharedMemorySize, smem128);
    cudaFuncSetAttribute(k_mma<64>,  cudaFuncAttributeMaxDynamicSharedMemorySize, smem64);

    const int mmaGrid = (N_NODES + 127) / 128;       // 782
    const int aggGrid = (N_NODES * 32 + 255) / 256;  // one warp per node

    // ---- CSR build (every call; deterministic result) ----
    k_zero_int<<<(N_NODES + 255) / 256, 256>>>(deg, N_NODES);
    k_hist<<<(N_EDGES + 255) / 256, 256>>>(ei, deg);
    k_scan_local<<<NB, 1024>>>(deg, rowp, bsum);
    k_scan_add<<<NB, 1024>>>(rowp, bsum, cursor);
    k_fill<<<(N_EDGES + 255) / 256, 256>>>(ei, cursor, csr);

    // ---- splits ----
    k_split_w<<<(20480 + 255) / 256, 256>>>(Wl0, Wr0, Wl1, Wr1, Wl2, Wr2, wbhi, wblo);
    k_split_x<<<(N_NODES * 32 + 255) / 256, 256>>>(x, ahi, alo);

    // ---- layer 0: x -> h (64) ----
    k_mma<128><<<mmaGrid, 256, smem128>>>(ahi, alo, wbhi, wblo, y);
    k_agg64<<<aggGrid, 256>>>(rowp, deg, csr, y, b0, ahi, alo);

    // ---- layer 1: h -> h (64) ----
    k_mma<128><<<mmaGrid, 256, smem128>>>(ahi, alo, wbhi + 8192, wblo + 8192, y);
    k_agg64<<<aggGrid, 256>>>(rowp, deg, csr, y, b1, ahi, alo);

    // ---- layer 2: h -> out (32, no activation) ----
    k_mma<64><<<mmaGrid, 256, smem64>>>(ahi, alo, wbhi + 16384, wblo + 16384, y);
    k_agg32<<<aggGrid, 256>>>(rowp, deg, csr, y, b2, out);
}

// round 17
// speedup vs baseline: 1.2582x; 1.0553x over previous
#include <cuda_runtime.h>
#include <cuda_bf16.h>
#include <cstdint>

#define N_NODES 100000
#define N_EDGES 1600000
#define NB 98  // ceil(N_NODES / 1024)

// ---------------- scratch (no allocations allowed) ----------------
__device__ float g_y[(size_t)N_NODES * 128];          // GEMM output [yl | yr] fp32
__device__ __nv_bfloat16 g_ahi[(size_t)N_NODES * 64]; // activation hi part
__device__ __nv_bfloat16 g_alo[(size_t)N_NODES * 64]; // activation lo part
__device__ __nv_bfloat16 g_wbhi[20480];               // W [n][k] bf16 hi: L0@0, L1@8192, L2@16384
__device__ __nv_bfloat16 g_wblo[20480];
__device__ int g_deg[N_NODES];
__device__ int g_rowp[N_NODES];
__device__ int g_cursor[N_NODES];
__device__ int g_csr[N_EDGES];
__device__ int g_bsum[128];

// ---------------- CSR build ----------------
__global__ void k_zero_int(int* __restrict__ p, int n) {
    int i = blockIdx.x * blockDim.x + threadIdx.x;
    if (i < n) p[i] = 0;
}

__global__ void k_hist(const int* __restrict__ ei, int* __restrict__ deg) {
    int i = blockIdx.x * blockDim.x + threadIdx.x;
    if (i < N_EDGES) atomicAdd(deg + ei[N_EDGES + i], 1);
}

__global__ __launch_bounds__(1024) void k_scan_local(
    const int* __restrict__ deg, int* __restrict__ rowp, int* __restrict__ bsum) {
    __shared__ int s[1024];
    int t = threadIdx.x;
    int i = blockIdx.x * 1024 + t;
    int v = (i < N_NODES) ? deg[i] : 0;
    s[t] = v;
    __syncthreads();
#pragma unroll
    for (int d = 1; d < 1024; d <<= 1) {
        int x = (t >= d) ? s[t - d] : 0;
        __syncthreads();
        s[t] += x;
        __syncthreads();
    }
    if (i < N_NODES) rowp[i] = s[t] - v;  // exclusive (block-local)
    if (t == 1023) bsum[blockIdx.x] = s[1023];
}

// add cross-block offsets (computed in-kernel from bsum) and init cursor
__global__ __launch_bounds__(1024) void k_scan_add(
    int* __restrict__ rowp, const int* __restrict__ bsum, int* __restrict__ cursor) {
    __shared__ int boff;
    int b = blockIdx.x;
    int t = threadIdx.x;
    if (t < 32) {
        int part = 0;
        for (int j = t; j < b; j += 32) part += bsum[j];
#pragma unroll
        for (int d = 16; d > 0; d >>= 1)
            part += __shfl_down_sync(0xFFFFFFFF, part, d);
        if (t == 0) boff = part;
    }
    __syncthreads();
    int i = b * 1024 + t;
    if (i < N_NODES) {
        int r = rowp[i] + boff;
        rowp[i] = r;
        cursor[i] = r;
    }
}

__global__ void k_fill(const int* __restrict__ ei, int* __restrict__ cursor,
                       int* __restrict__ csr) {
    int i = blockIdx.x * blockDim.x + threadIdx.x;
    if (i < N_EDGES) {
        int src = ei[i];
        int dst = ei[N_EDGES + i];
        int pos = atomicAdd(cursor + dst, 1);
        csr[pos] = src;
    }
}

// ---------------- bf16 weight split ----------------
// W combined as B[n][k] = (n<f ? Wl[k][n] : Wr[k][n-f]), [N=2f, K=64] bf16 row-major
__global__ void k_split_w(const float* __restrict__ Wl0, const float* __restrict__ Wr0,
                          const float* __restrict__ Wl1, const float* __restrict__ Wr1,
                          const float* __restrict__ Wl2, const float* __restrict__ Wr2,
                          __nv_bfloat16* __restrict__ bh, __nv_bfloat16* __restrict__ bl) {
    int i = blockIdx.x * blockDim.x + threadIdx.x;
    if (i >= 20480) return;
    const float *Wl, *Wr;
    int f, base, li;
    if (i < 8192)       { Wl = Wl0; Wr = Wr0; f = 64; base = 0;     li = i; }
    else if (i < 16384) { Wl = Wl1; Wr = Wr1; f = 64; base = 8192;  li = i - 8192; }
    else                { Wl = Wl2; Wr = Wr2; f = 32; base = 16384; li = i - 16384; }
    int n = li >> 6, k = li & 63;
    float v = (n < f) ? Wl[k * f + n] : Wr[k * f + (n - f)];
    __nv_bfloat16 h = __float2bfloat16(v);
    bh[base + li] = h;
    bl[base + li] = __float2bfloat16(v - __bfloat162float(h));
}

// ---------------- tensor GEMM via mma.sync m16n8k16 bf16, 3-term split --------------
// C[128-tile, NOUT] = A[*,64] @ B^T, B stored [NOUT][64].
// acc += Ahi*Bhi + Alo*Bhi + Ahi*Blo  (fp32 accumulators)
// F32A: A is fp32 in gmem; hi/lo split happens during smem staging (layer 0).
__device__ __forceinline__ void mma16816(float* c, const uint32_t* a, const uint32_t* b) {
    asm volatile(
        "mma.sync.aligned.m16n8k16.row.col.f32.bf16.bf16.f32 "
        "{%0,%1,%2,%3}, {%4,%5,%6,%7}, {%8,%9}, {%0,%1,%2,%3};"
        : "+f"(c[0]), "+f"(c[1]), "+f"(c[2]), "+f"(c[3])
        : "r"(a[0]), "r"(a[1]), "r"(a[2]), "r"(a[3]), "r"(b[0]), "r"(b[1]));
}

template <int NOUT, bool F32A>
__global__ __launch_bounds__(256) void k_mma(
    const void* __restrict__ A0, const void* __restrict__ A1,
    const __nv_bfloat16* __restrict__ Bhi, const __nv_bfloat16* __restrict__ Blo,
    float* __restrict__ C) {
    constexpr int NT = NOUT / 8;  // n-tiles per warp
    // smem rows padded to 72 bf16 (36 b32 words) -> frag LDS banks (4g+t)%32: conflict-free
    extern __shared__ __align__(16) __nv_bfloat16 sm[];
    __nv_bfloat16* sAh = sm;                 // 128 x 72
    __nv_bfloat16* sAl = sAh + 128 * 72;
    __nv_bfloat16* sBh = sAl + 128 * 72;     // NOUT x 72
    __nv_bfloat16* sBl = sBh + NOUT * 72;

    const int tid = threadIdx.x;
    const int base = blockIdx.x * 128;

    if (F32A) {
        // stage A from fp32: 128 rows x 64 fp32 = 16 float4 per row; split to hi/lo
        const float* X = (const float*)A0;
        for (int i = tid; i < 2048; i += 256) {
            int row = i >> 4, c = i & 15;
            int node = base + row;
            if (node >= N_NODES) node = N_NODES - 1;
            float4 v = *((const float4*)(X + (size_t)node * 64) + c);
            __nv_bfloat162 h0, h1, l0, l1;
            h0.x = __float2bfloat16(v.x); h0.y = __float2bfloat16(v.y);
            h1.x = __float2bfloat16(v.z); h1.y = __float2bfloat16(v.w);
            l0.x = __float2bfloat16(v.x - __bfloat162float(h0.x));
            l0.y = __float2bfloat16(v.y - __bfloat162float(h0.y));
            l1.x = __float2bfloat16(v.z - __bfloat162float(h1.x));
            l1.y = __float2bfloat16(v.w - __bfloat162float(h1.y));
            __nv_bfloat162* ph = (__nv_bfloat162*)(sAh + row * 72 + c * 4);
            ph[0] = h0; ph[1] = h1;
            __nv_bfloat162* pl = (__nv_bfloat162*)(sAl + row * 72 + c * 4);
            pl[0] = l0; pl[1] = l1;
        }
    } else {
        // stage A (hi+lo): 128 rows x 64 bf16 = 8 int4 per row (128 B/row)
        const __nv_bfloat16* Ahi = (const __nv_bfloat16*)A0;
        const __nv_bfloat16* Alo = (const __nv_bfloat16*)A1;
        for (int i = tid; i < 1024; i += 256) {
            int row = i >> 3, c = i & 7;
            int node = base + row;
            if (node >= N_NODES) node = N_NODES - 1;
            *(int4*)(sAh + row * 72 + c * 8) = *((const int4*)(Ahi + (size_t)node * 64) + c);
            *(int4*)(sAl + row * 72 + c * 8) = *((const int4*)(Alo + (size_t)node * 64) + c);
        }
    }
    // stage B (hi+lo): NOUT rows x 64 bf16 = 8 int4 per row
    for (int i = tid; i < NOUT * 8; i += 256) {
        int row = i >> 3, c = i & 7;
        *(int4*)(sBh + row * 72 + c * 8) = *((const int4*)(Bhi + row * 64) + c);
        *(int4*)(sBl + row * 72 + c * 8) = *((const int4*)(Blo + row * 64) + c);
    }
    __syncthreads();

    const int wid = tid >> 5, lane = tid & 31;
    const int g = lane >> 2, t = lane & 3;

    const uint32_t* wAh = (const uint32_t*)sAh;
    const uint32_t* wAl = (const uint32_t*)sAl;
    const uint32_t* wBh = (const uint32_t*)sBh;
    const uint32_t* wBl = (const uint32_t*)sBl;

    // preload A fragments for all 4 k-tiles (hi and lo), register-resident
    uint32_t ah[4][4], al[4][4];
    const int arow = (wid * 16 + g) * 36;
#pragma unroll
    for (int kt = 0; kt < 4; kt++) {
        int w0 = arow + kt * 8 + t;
        ah[kt][0] = wAh[w0];
        ah[kt][1] = wAh[w0 + 8 * 36];
        ah[kt][2] = wAh[w0 + 4];
        ah[kt][3] = wAh[w0 + 8 * 36 + 4];
        al[kt][0] = wAl[w0];
        al[kt][1] = wAl[w0 + 8 * 36];
        al[kt][2] = wAl[w0 + 4];
        al[kt][3] = wAl[w0 + 8 * 36 + 4];
    }

    float acc[NT][4];
#pragma unroll
    for (int nt = 0; nt < NT; nt++)
#pragma unroll
        for (int q = 0; q < 4; q++) acc[nt][q] = 0.f;

#pragma unroll
    for (int nt = 0; nt < NT; nt++) {
#pragma unroll
        for (int kt = 0; kt < 4; kt++) {
            int wb = (nt * 8 + g) * 36 + kt * 8 + t;
            uint32_t bh[2] = {wBh[wb], wBh[wb + 4]};
            mma16816(acc[nt], ah[kt], bh);
            mma16816(acc[nt], al[kt], bh);
            uint32_t bl[2] = {wBl[wb], wBl[wb + 4]};
            mma16816(acc[nt], ah[kt], bl);
        }
    }

    // epilogue: c0,c1 -> row (g), cols 2t,2t+1 of n-tile; c2,c3 -> row g+8
    const int r0 = base + wid * 16 + g;
#pragma unroll
    for (int nt = 0; nt < NT; nt++) {
        int col = nt * 8 + 2 * t;
        if (r0 < N_NODES)
            *(float2*)(C + (size_t)r0 * NOUT + col) = make_float2(acc[nt][0], acc[nt][1]);
        if (r0 + 8 < N_NODES)
            *(float2*)(C + (size_t)(r0 + 8) * NOUT + col) = make_float2(acc[nt][2], acc[nt][3]);
    }
}

// ---------------- fused aggregate+combine, F=64, bf16-split output ----------------
__global__ __launch_bounds__(256) void k_agg64(
    const int* __restrict__ rowp, const int* __restrict__ deg,
    const int* __restrict__ csr, const float* __restrict__ Y,
    const float* __restrict__ bias, __nv_bfloat16* __restrict__ ohi,
    __nv_bfloat16* __restrict__ olo) {
    int warp = (blockIdx.x * blockDim.x + threadIdx.x) >> 5;
    int lane = threadIdx.x & 31;
    if (warp >= N_NODES) return;
    int start = rowp[warp];
    int cnt = deg[warp];
    const float* Ycol = Y + lane * 2;

    float ax = 0.f, ay = 0.f;
    int j = 0;
    for (; j + 4 <= cnt; j += 4) {
        int s0 = __ldg(csr + start + j + 0);
        int s1 = __ldg(csr + start + j + 1);
        int s2 = __ldg(csr + start + j + 2);
        int s3 = __ldg(csr + start + j + 3);
        float2 v0 = *(const float2*)(Ycol + (size_t)s0 * 128);
        float2 v1 = *(const float2*)(Ycol + (size_t)s1 * 128);
        float2 v2 = *(const float2*)(Ycol + (size_t)s2 * 128);
        float2 v3 = *(const float2*)(Ycol + (size_t)s3 * 128);
        ax += v0.x; ay += v0.y;
        ax += v1.x; ay += v1.y;
        ax += v2.x; ay += v2.y;
        ax += v3.x; ay += v3.y;
    }
    for (; j < cnt; j++) {
        int s = __ldg(csr + start + j);
        float2 v = *(const float2*)(Ycol + (size_t)s * 128);
        ax += v.x; ay += v.y;
    }

    float dinv = 1.0f / fmaxf((float)cnt, 1.0f);
    float2 r = *(const float2*)(Y + (size_t)warp * 128 + 64 + lane * 2);
    float2 bb = *(const float2*)(bias + lane * 2);
    float ox = ax * dinv + r.x + bb.x;
    float oy = ay * dinv + r.y + bb.y;
    ox = ox > 0.f ? ox : (__expf(ox) - 1.f);
    oy = oy > 0.f ? oy : (__expf(oy) - 1.f);

    __nv_bfloat16 hx = __float2bfloat16(ox);
    __nv_bfloat16 hy = __float2bfloat16(oy);
    __nv_bfloat162 hv; hv.x = hx; hv.y = hy;
    __nv_bfloat162 lv;
    lv.x = __float2bfloat16(ox - __bfloat162float(hx));
    lv.y = __float2bfloat16(oy - __bfloat162float(hy));
    *(__nv_bfloat162*)(ohi + (size_t)warp * 64 + lane * 2) = hv;
    *(__nv_bfloat162*)(olo + (size_t)warp * 64 + lane * 2) = lv;
}

// ---------------- fused aggregate+combine, F=32 (final layer, fp32 out) -----------
__global__ __launch_bounds__(256) void k_agg32(
    const int* __restrict__ rowp, const int* __restrict__ deg,
    const int* __restrict__ csr, const float* __restrict__ Y,
    const float* __restrict__ bias, float* __restrict__ out) {
    int warp = (blockIdx.x * blockDim.x + threadIdx.x) >> 5;
    int lane = threadIdx.x & 31;
    if (warp >= N_NODES) return;
    int start = rowp[warp];
    int cnt = deg[warp];
    const float* Ycol = Y + lane;

    float ax = 0.f;
    int j = 0;
    for (; j + 4 <= cnt; j += 4) {
        int s0 = __ldg(csr + start + j + 0);
        int s1 = __ldg(csr + start + j + 1);
        int s2 = __ldg(csr + start + j + 2);
        int s3 = __ldg(csr + start + j + 3);
        ax += Ycol[(size_t)s0 * 64];
        ax += Ycol[(size_t)s1 * 64];
        ax += Ycol[(size_t)s2 * 64];
        ax += Ycol[(size_t)s3 * 64];
    }
    for (; j < cnt; j++) {
        int s = __ldg(csr + start + j);
        ax += Ycol[(size_t)s * 64];
    }

    float dinv = 1.0f / fmaxf((float)cnt, 1.0f);
    float r = Y[(size_t)warp * 64 + 32 + lane];
    out[(size_t)warp * 32 + lane] = ax * dinv + r + bias[lane];
}

// ---------------- host ----------------
extern "C" void kernel_launch(void* const* d_in, const int* in_sizes, int n_in,
                              void* d_out, int out_size) {
    const float* x   = (const float*)d_in[0];
    const int*   ei  = (const int*)d_in[1];
    const float* Wl0 = (const float*)d_in[2];
    const float* Wr0 = (const float*)d_in[3];
    const float* b0  = (const float*)d_in[4];
    const float* Wl1 = (const float*)d_in[5];
    const float* Wr1 = (const float*)d_in[6];
    const float* b1  = (const float*)d_in[7];
    const float* Wl2 = (const float*)d_in[8];
    const float* Wr2 = (const float*)d_in[9];
    const float* b2  = (const float*)d_in[10];
    float* out = (float*)d_out;

    float* y;
    __nv_bfloat16 *ahi, *alo, *wbhi, *wblo;
    int *deg, *rowp, *cursor, *csr, *bsum;
    cudaGetSymbolAddress((void**)&y, g_y);
    cudaGetSymbolAddress((void**)&ahi, g_ahi);
    cudaGetSymbolAddress((void**)&alo, g_alo);
    cudaGetSymbolAddress((void**)&wbhi, g_wbhi);
    cudaGetSymbolAddress((void**)&wblo, g_wblo);
    cudaGetSymbolAddress((void**)&deg, g_deg);
    cudaGetSymbolAddress((void**)&rowp, g_rowp);
    cudaGetSymbolAddress((void**)&cursor, g_cursor);
    cudaGetSymbolAddress((void**)&csr, g_csr);
    cudaGetSymbolAddress((void**)&bsum, g_bsum);

    // side stream + events, created once outside graph capture (the first
    // correctness call is not captured; replays reuse the same handles)
    static cudaStream_t sB = nullptr;
    static cudaEvent_t evFork = nullptr, evJoin = nullptr;
    if (sB == nullptr) {
        cudaStreamCreateWithFlags(&sB, cudaStreamNonBlocking);
        cudaEventCreateWithFlags(&evFork, cudaEventDisableTiming);
        cudaEventCreateWithFlags(&evJoin, cudaEventDisableTiming);
    }

    const int smem128 = (128 * 72 * 2 + 128 * 72 * 2) * 2;  // 73728
    const int smem64  = (128 * 72 * 2 + 64 * 72 * 2) * 2;   // 55296
    cudaFuncSetAttribute(k_mma<128, true>,  cudaFuncAttributeMaxDynamicSharedMemorySize, smem128);
    cudaFuncSetAttribute(k_mma<128, false>, cudaFuncAttributeMaxDynamicSharedMemorySize, smem128);
    cudaFuncSetAttribute(k_mma<64, false>,  cudaFuncAttributeMaxDynamicSharedMemorySize, smem64);

    const int mmaGrid = (N_NODES + 127) / 128;       // 782
    const int aggGrid = (N_NODES * 32 + 255) / 256;  // one warp per node

    // ---- fork: CSR build on side stream (independent of splits + layer-0 GEMM) ----
    cudaEventRecord(evFork, 0);
    cudaStreamWaitEvent(sB, evFork, 0);
    k_zero_int<<<(N_NODES + 255) / 256, 256, 0, sB>>>(deg, N_NODES);
    k_hist<<<(N_EDGES + 255) / 256, 256, 0, sB>>>(ei, deg);
    k_scan_local<<<NB, 1024, 0, sB>>>(deg, rowp, bsum);
    k_scan_add<<<NB, 1024, 0, sB>>>(rowp, bsum, cursor);
    k_fill<<<(N_EDGES + 255) / 256, 256, 0, sB>>>(ei, cursor, csr);
    cudaEventRecord(evJoin, sB);

    // ---- main stream: weight split + layer-0 GEMM (reads fp32 x directly) ----
    k_split_w<<<(20480 + 255) / 256, 256>>>(Wl0, Wr0, Wl1, Wr1, Wl2, Wr2, wbhi, wblo);
    k_mma<128, true><<<mmaGrid, 256, smem128>>>(x, nullptr, wbhi, wblo, y);

    // ---- join: aggregation needs the CSR ----
    cudaStreamWaitEvent(0, evJoin, 0);
    k_agg64<<<aggGrid, 256>>>(rowp, deg, csr, y, b0, ahi, alo);

    // ---- layer 1: h -> h (64) ----
    k_mma<128, false><<<mmaGrid, 256, smem128>>>(ahi, alo, wbhi + 8192, wblo + 8192, y);
    k_agg64<<<aggGrid, 256>>>(rowp, deg, csr, y, b1, ahi, alo);

    // ---- layer 2: h -> out (32, no activation) ----
    k_mma<64, false><<<mmaGrid, 256, smem64>>>(ahi, alo, wbhi + 16384, wblo + 16384, y);
    k_agg32<<<aggGrid, 256>>>(rowp, deg, csr, y, b2, out);
}